// round 7
// baseline (speedup 1.0000x reference)
#include <cuda_runtime.h>
#include <math.h>

#define D_MODEL 1024
#define N_HEADS 8
#define HEAD_DIM 128
#define T_TOK 8193            // 1 class token + 8192 x rows
#define SS 8224               // padded score stride
#define S_NBLK 129            // 129 blocks * 64 tokens >= 8193
#define ATTN_SCALE 0.08838834764831845f   // 1/sqrt(128)

// ---------------- scratch (__device__ globals) ------------------------------
__device__ float g_u[N_HEADS * D_MODEL];
__device__ float g_c[N_HEADS];
__device__ float g_scores[N_HEADS * SS];
__device__ float g_pM[S_NBLK * N_HEADS];
__device__ float g_pZ[S_NBLK * N_HEADS];
__device__ float g_wpart[S_NBLK * N_HEADS * D_MODEL];
__device__ float g_w[N_HEADS * D_MODEL];
__device__ float g_attn0[D_MODEL];
__device__ float g_out0[D_MODEL];

// ---------------- helpers ---------------------------------------------------
__device__ __forceinline__ float warp_sum(float v) {
#pragma unroll
    for (int o = 16; o; o >>= 1) v += __shfl_xor_sync(0xffffffffu, v, o);
    return v;
}

// y[r] = b[r] + W[r,:] . v
__global__ void matvec_warp(const float* __restrict__ W, const float* __restrict__ v,
                            const float* __restrict__ b, float* __restrict__ y) {
    int warp = (blockIdx.x * blockDim.x + threadIdx.x) >> 5;
    int lane = threadIdx.x & 31;
    if (warp >= D_MODEL) return;
    const float* wr = W + (size_t)warp * D_MODEL;
    float acc = 0.f;
#pragma unroll
    for (int i = 0; i < D_MODEL / 32; i++)
        acc += wr[i * 32 + lane] * v[i * 32 + lane];
    acc = warp_sum(acc);
    if (lane == 0) y[warp] = acc + b[warp];
}

// attn0[j] = bv[j] + Wv[j,:] . w[head(j),:]
__global__ void attn0_kernel(const float* __restrict__ Wv, const float* __restrict__ bv) {
    int warp = (blockIdx.x * blockDim.x + threadIdx.x) >> 5;
    int lane = threadIdx.x & 31;
    if (warp >= D_MODEL) return;
    const float* wr = Wv + (size_t)warp * D_MODEL;
    const float* wv = g_w + (size_t)(warp >> 7) * D_MODEL;
    float acc = 0.f;
#pragma unroll
    for (int i = 0; i < D_MODEL / 32; i++)
        acc += wr[i * 32 + lane] * wv[i * 32 + lane];
    acc = warp_sum(acc);
    if (lane == 0) g_attn0[warp] = acc + bv[warp];
}

// ---- fused q0 + u + c: 32 blocks, block b -> head h=b/4, quarter q=b%3 ------
// Stage A: q0_h = Wq_h @ cls + bq_h (warp-per-row, cls in shared)
// Stage B: u[h,d] = scale * sum_r Wk[h*128+r, d] * q0_h[r]
__global__ __launch_bounds__(256)
void compute_u2(const float* __restrict__ Wq, const float* __restrict__ bq,
                const float* __restrict__ Wk, const float* __restrict__ bk,
                const float* __restrict__ cls) {
    __shared__ float sq[HEAD_DIM];
    __shared__ float scl[D_MODEL];
    int tid = threadIdx.x;
    int w = tid >> 5, lane = tid & 31;
    int h = blockIdx.x >> 2;
    int qtr = blockIdx.x & 3;

    for (int i = tid; i < D_MODEL; i += 256) scl[i] = cls[i];
    __syncthreads();

    // Stage A: 8 warps x 16 rows
#pragma unroll
    for (int rr = 0; rr < 16; rr++) {
        int r = w * 16 + rr;
        const float* wr = Wq + (size_t)(h * HEAD_DIM + r) * D_MODEL;
        float a = 0.f;
#pragma unroll
        for (int i = 0; i < D_MODEL / 32; i++)
            a += wr[i * 32 + lane] * scl[i * 32 + lane];
        a = warp_sum(a);
        if (lane == 0) sq[r] = a + bq[h * HEAD_DIM + r];
    }
    __syncthreads();

    // c[h] = scale * q0_h . bk_h (warp 0 of quarter-0 block writes)
    if (w == 0 && qtr == 0) {
        float a = 0.f;
#pragma unroll
        for (int i = 0; i < HEAD_DIM / 32; i++)
            a += sq[i * 32 + lane] * bk[h * HEAD_DIM + i * 32 + lane];
        a = warp_sum(a);
        if (lane == 0) g_c[h] = a * ATTN_SCALE;
    }

    // Stage B: u for d = qtr*256 + tid
    int d = qtr * 256 + tid;
    const float* wp = Wk + (size_t)h * HEAD_DIM * D_MODEL + d;
    float acc = 0.f;
#pragma unroll 16
    for (int r = 0; r < HEAD_DIM; r++) acc += wp[(size_t)r * D_MODEL] * sq[r];
    g_u[h * D_MODEL + d] = acc * ATTN_SCALE;
}

// ---- fused: scores + block softmax partials + weighted token partial sums --
__global__ __launch_bounds__(256, 1)
void fused_kernel(const float* __restrict__ x, const float* __restrict__ cls) {
    __shared__ float4 su4[N_HEADS * 256];
    __shared__ float sc[N_HEADS];
    __shared__ float ss[N_HEADS][64];
    __shared__ float sp[N_HEADS][64];

    int tid = threadIdx.x;
    const float4* gu4 = (const float4*)g_u;
#pragma unroll
    for (int k = 0; k < 8; k++) su4[k * 256 + tid] = gu4[k * 256 + tid];
    if (tid < N_HEADS) sc[tid] = g_c[tid];
    __syncthreads();

    int w = tid >> 5, lane = tid & 31;
    int t0 = blockIdx.x * 64 + w * 8;

    const float4* rp[8];
    bool val[8];
#pragma unroll
    for (int j = 0; j < 8; j++) {
        int t = t0 + j;
        val[j] = (t < T_TOK);
        const float* p = (t == 0) ? cls : (val[j] ? x + (size_t)(t - 1) * D_MODEL : cls);
        rp[j] = (const float4*)p;
    }

    float acc[8][8];
#pragma unroll
    for (int j = 0; j < 8; j++)
#pragma unroll
        for (int h = 0; h < 8; h++) acc[j][h] = 0.f;

#pragma unroll
    for (int i = 0; i < 8; i++) {
        int f = i * 32 + lane;
        float4 u4[8];
#pragma unroll
        for (int h = 0; h < 8; h++) u4[h] = su4[h * 256 + f];
#pragma unroll
        for (int j = 0; j < 8; j++) {
            float4 tv = rp[j][f];
#pragma unroll
            for (int h = 0; h < 8; h++) {
                acc[j][h] += tv.x * u4[h].x;
                acc[j][h] += tv.y * u4[h].y;
                acc[j][h] += tv.z * u4[h].z;
                acc[j][h] += tv.w * u4[h].w;
            }
        }
    }

#pragma unroll
    for (int j = 0; j < 8; j++)
#pragma unroll
        for (int h = 0; h < 8; h++) {
            float s = acc[j][h];
#pragma unroll
            for (int o = 16; o; o >>= 1) s += __shfl_xor_sync(0xffffffffu, s, o);
            acc[j][h] = s;
        }

    float myv[8];
#pragma unroll
    for (int j = 0; j < 8; j++) {
        float v = acc[j][0];
#pragma unroll
        for (int h = 1; h < 8; h++) if (lane == h) v = acc[j][h];
        myv[j] = v;
    }

    if (lane < N_HEADS) {
        float c = sc[lane];
#pragma unroll
        for (int j = 0; j < 8; j++) {
            float s = val[j] ? (myv[j] + c) : -3e38f;
            ss[lane][w * 8 + j] = s;
            if (val[j]) g_scores[lane * SS + t0 + j] = s;
        }
    }
    __syncthreads();

    if (w < N_HEADS) {
        int h = w;
        float v0 = ss[h][lane], v1 = ss[h][lane + 32];
        float m = fmaxf(v0, v1);
#pragma unroll
        for (int o = 16; o; o >>= 1) m = fmaxf(m, __shfl_xor_sync(0xffffffffu, m, o));
        float e0 = __expf(v0 - m), e1 = __expf(v1 - m);
        sp[h][lane] = e0;
        sp[h][lane + 32] = e1;
        float z = warp_sum(e0 + e1);
        if (lane == 0) {
            g_pM[blockIdx.x * N_HEADS + h] = m;
            g_pZ[blockIdx.x * N_HEADS + h] = z;
        }
    }
    __syncthreads();

    float4 wacc[N_HEADS];
#pragma unroll
    for (int h = 0; h < N_HEADS; h++) wacc[h] = make_float4(0.f, 0.f, 0.f, 0.f);
    int d4 = tid * 4;
    int base = blockIdx.x * 64;
    int n = min(64, T_TOK - base);

#pragma unroll 4
    for (int i = 0; i < n; i++) {
        int gt = base + i;
        const float* tp = (gt == 0) ? cls : x + (size_t)(gt - 1) * D_MODEL;
        float4 tv = *reinterpret_cast<const float4*>(tp + d4);
#pragma unroll
        for (int h = 0; h < N_HEADS; h++) {
            float p = sp[h][i];
            wacc[h].x += p * tv.x;
            wacc[h].y += p * tv.y;
            wacc[h].z += p * tv.z;
            wacc[h].w += p * tv.w;
        }
    }
#pragma unroll
    for (int h = 0; h < N_HEADS; h++)
        *reinterpret_cast<float4*>(
            &g_wpart[(size_t)blockIdx.x * (N_HEADS * D_MODEL) + h * D_MODEL + d4]) = wacc[h];
}

// ---- finalize: blocks 0..63 merge w partials (8 threads/float4-col);
//      blocks 64..95 write A -------------------------------------------------
__global__ __launch_bounds__(256)
void finalize2(float* __restrict__ out, int out_size) {
    __shared__ float sM[N_HEADS], sZi[N_HEADS];
    __shared__ float sf[S_NBLK];

    int tid = threadIdx.x;
    int w = tid >> 5, lane = tid & 31;

    // global (M, Z) per head
    if (w < N_HEADS) {
        int h = w;
        float m = -3e38f, z = 0.f;
        for (int b = lane; b < S_NBLK; b += 32) {
            float bm = g_pM[b * N_HEADS + h];
            float bz = g_pZ[b * N_HEADS + h];
            float nm = fmaxf(m, bm);
            z = z * __expf(m - nm) + bz * __expf(bm - nm);
            m = nm;
        }
#pragma unroll
        for (int o = 16; o; o >>= 1) {
            float om = __shfl_xor_sync(0xffffffffu, m, o);
            float oz = __shfl_xor_sync(0xffffffffu, z, o);
            float nm = fmaxf(m, om);
            z = z * __expf(m - nm) + oz * __expf(om - nm);
            m = nm;
        }
        if (lane == 0) { sM[h] = m; sZi[h] = 1.0f / z; }
    }
    __syncthreads();

    if (blockIdx.x < 64) {
        // block covers 128 consecutive idx (h constant), 8 threads per float4-col
        int idx0 = blockIdx.x * 128;
        int h = idx0 >> 10;
        float M = sM[h], Zi = sZi[h];
        for (int b = tid; b < S_NBLK; b += 256)
            sf[b] = __expf(g_pM[b * N_HEADS + h] - M) * Zi;
        __syncthreads();

        int col4 = (idx0 >> 2) + (tid >> 3);   // float4 column index
        int sub = tid & 7;
        const float4* wp4 = (const float4*)g_wpart;
        float4 a = make_float4(0.f, 0.f, 0.f, 0.f);
        for (int b = sub; b < S_NBLK; b += 8) {
            float4 v = wp4[(size_t)b * 2048 + col4];
            float s = sf[b];
            a.x += s * v.x; a.y += s * v.y; a.z += s * v.z; a.w += s * v.w;
        }
#pragma unroll
        for (int o = 4; o; o >>= 1) {
            a.x += __shfl_xor_sync(0xffffffffu, a.x, o);
            a.y += __shfl_xor_sync(0xffffffffu, a.y, o);
            a.z += __shfl_xor_sync(0xffffffffu, a.z, o);
            a.w += __shfl_xor_sync(0xffffffffu, a.w, o);
        }
        if (sub == 0) ((float4*)g_w)[col4] = a;
    } else {
        // A[s] = mean_h p[h, s+1]
        int s = (blockIdx.x - 64) * 256 + tid;
        float a = 0.f;
#pragma unroll
        for (int h = 0; h < N_HEADS; h++)
            a += __expf(g_scores[h * SS + s + 1] - sM[h]) * sZi[h];
        a *= 0.125f;
        int oi = 7 + s;
        if (oi < out_size) out[oi] = a;
    }
}

// logits, softmax, argmax -> out[0..6]
__global__ void final_kernel(const float* __restrict__ Wc, const float* __restrict__ bc,
                             float* __restrict__ out, int out_size) {
    __shared__ float slog[2];
    int wid = threadIdx.x >> 5, lane = threadIdx.x & 31;
    if (wid < 2) {
        float acc = 0.f;
#pragma unroll
        for (int i = 0; i < D_MODEL / 32; i++)
            acc += Wc[wid * D_MODEL + i * 32 + lane] * g_out0[i * 32 + lane];
        acc = warp_sum(acc);
        if (lane == 0) slog[wid] = acc + bc[wid];
    }
    __syncthreads();
    if (threadIdx.x == 0 && out_size >= 7) {
        float l0 = slog[0], l1 = slog[1];
        float mx = fmaxf(l0, l1);
        float e0 = __expf(l0 - mx), e1 = __expf(l1 - mx);
        float z = e0 + e1;
        float p0 = e0 / z, p1 = e1 / z;
        float am = (p1 > p0) ? 1.0f : 0.0f;
        out[0] = l0; out[1] = l1;
        out[2] = p0; out[3] = p1;
        out[4] = am;
        out[5] = p0; out[6] = p1;
    }
}

// ---------------- launch -----------------------------------------------------
extern "C" void kernel_launch(void* const* d_in, const int* in_sizes, int n_in,
                              void* d_out, int out_size) {
    const float* x   = (const float*)d_in[0];
    const float* cls = (const float*)d_in[1];
    const float* Wq  = (const float*)d_in[2];
    const float* bq  = (const float*)d_in[3];
    const float* Wk  = (const float*)d_in[4];
    const float* bk  = (const float*)d_in[5];
    const float* Wv  = (const float*)d_in[6];
    const float* bv  = (const float*)d_in[7];
    const float* Wo  = (const float*)d_in[8];
    const float* bo  = (const float*)d_in[9];
    const float* Wc  = (const float*)d_in[10];
    const float* bc  = (const float*)d_in[11];
    float* out = (float*)d_out;

    float* gattn; cudaGetSymbolAddress((void**)&gattn, g_attn0);
    float* gout0; cudaGetSymbolAddress((void**)&gout0, g_out0);

    compute_u2<<<32, 256>>>(Wq, bq, Wk, bk, cls);       // q0 + u + c fused
    fused_kernel<<<S_NBLK, 256>>>(x, cls);              // scores + partials (1 x pass)
    finalize2<<<96, 256>>>(out, out_size);              // merge -> w, write A
    attn0_kernel<<<128, 256>>>(Wv, bv);                 // attn0
    matvec_warp<<<128, 256>>>(Wo, gattn, bo, gout0);    // out0
    final_kernel<<<1, 64>>>(Wc, bc, out, out_size);     // logits etc.
}

// round 10
// speedup vs baseline: 1.4297x; 1.4297x over previous
#include <cuda_runtime.h>
#include <math.h>

#define D_MODEL 1024
#define N_HEADS 8
#define HEAD_DIM 128
#define T_TOK 8193            // 1 class token + 8192 x rows
#define SS 8224               // padded score stride
#define S_NBLK 129            // 129 blocks * 64 tokens >= 8193
#define ATTN_SCALE 0.08838834764831845f   // 1/sqrt(128)

// ---------------- scratch (__device__ globals) ------------------------------
__device__ float g_q0[D_MODEL];
__device__ float g_u[N_HEADS * D_MODEL];
__device__ float g_c[N_HEADS];
__device__ float g_scores[N_HEADS * SS];
__device__ float g_pM[S_NBLK * N_HEADS];
__device__ float g_pZ[S_NBLK * N_HEADS];
__device__ float g_wpart[S_NBLK * N_HEADS * D_MODEL];
__device__ float g_w[N_HEADS * D_MODEL];
__device__ float g_attn0[D_MODEL];
__device__ float g_out0[D_MODEL];

// ---------------- helpers ---------------------------------------------------
__device__ __forceinline__ float warp_sum(float v) {
#pragma unroll
    for (int o = 16; o; o >>= 1) v += __shfl_xor_sync(0xffffffffu, v, o);
    return v;
}

// y[r] = b[r] + W[r,:] . v   (warp per row, float4 loads)
__global__ void matvec_warp(const float* __restrict__ W, const float* __restrict__ v,
                            const float* __restrict__ b, float* __restrict__ y) {
    int warp = (blockIdx.x * blockDim.x + threadIdx.x) >> 5;
    int lane = threadIdx.x & 31;
    if (warp >= D_MODEL) return;
    const float4* wr = (const float4*)(W + (size_t)warp * D_MODEL);
    const float4* vv = (const float4*)v;
    float acc = 0.f;
#pragma unroll
    for (int i = 0; i < D_MODEL / 128; i++) {
        float4 a = wr[i * 32 + lane];
        float4 c = vv[i * 32 + lane];
        acc += a.x * c.x + a.y * c.y + a.z * c.z + a.w * c.w;
    }
    acc = warp_sum(acc);
    if (lane == 0) y[warp] = acc + b[warp];
}

// attn0[j] = bv[j] + Wv[j,:] . w[head(j),:]   (float4)
__global__ void attn0_kernel(const float* __restrict__ Wv, const float* __restrict__ bv) {
    int warp = (blockIdx.x * blockDim.x + threadIdx.x) >> 5;
    int lane = threadIdx.x & 31;
    if (warp >= D_MODEL) return;
    const float4* wr = (const float4*)(Wv + (size_t)warp * D_MODEL);
    const float4* wv = (const float4*)(g_w + (size_t)(warp >> 7) * D_MODEL);
    float acc = 0.f;
#pragma unroll
    for (int i = 0; i < D_MODEL / 128; i++) {
        float4 a = wr[i * 32 + lane];
        float4 c = wv[i * 32 + lane];
        acc += a.x * c.x + a.y * c.y + a.z * c.z + a.w * c.w;
    }
    acc = warp_sum(acc);
    if (lane == 0) g_attn0[warp] = acc + bv[warp];
}

// u[h,d] = scale * sum_r Wk[h*128+r, d] * q0[h*128+r];  block 32: c[h]
__global__ void compute_u(const float* __restrict__ Wk, const float* __restrict__ bk) {
    if (blockIdx.x == 32) {
        int wid = threadIdx.x >> 5, lane = threadIdx.x & 31;
        if (wid < N_HEADS) {
            float acc = 0.f;
#pragma unroll
            for (int i = 0; i < HEAD_DIM / 32; i++) {
                int r = wid * HEAD_DIM + i * 32 + lane;
                acc += g_q0[r] * bk[r];
            }
            acc = warp_sum(acc);
            if (lane == 0) g_c[wid] = acc * ATTN_SCALE;
        }
        return;
    }
    __shared__ float sq[HEAD_DIM];
    int idx = blockIdx.x * 256 + threadIdx.x;
    int h = idx >> 10;
    if (threadIdx.x < HEAD_DIM) sq[threadIdx.x] = g_q0[h * HEAD_DIM + threadIdx.x];
    __syncthreads();
    const float* wp = Wk + (size_t)h * HEAD_DIM * D_MODEL + (idx & 1023);
    float acc = 0.f;
#pragma unroll 16
    for (int r = 0; r < HEAD_DIM; r++) acc += wp[(size_t)r * D_MODEL] * sq[r];
    g_u[idx] = acc * ATTN_SCALE;
}

// ---- fused: scores + block softmax partials + weighted token partial sums --
// 64 tokens per block, 129 blocks; x read from DRAM once.
__global__ __launch_bounds__(256, 1)
void fused_kernel(const float* __restrict__ x, const float* __restrict__ cls) {
    __shared__ float4 su4[N_HEADS * 256];
    __shared__ float sc[N_HEADS];
    __shared__ float ss[N_HEADS][64];
    __shared__ float sp[N_HEADS][64];

    int tid = threadIdx.x;
    const float4* gu4 = (const float4*)g_u;
#pragma unroll
    for (int k = 0; k < 8; k++) su4[k * 256 + tid] = gu4[k * 256 + tid];
    if (tid < N_HEADS) sc[tid] = g_c[tid];
    __syncthreads();

    int w = tid >> 5, lane = tid & 31;
    int t0 = blockIdx.x * 64 + w * 8;

    const float4* rp[8];
    bool val[8];
#pragma unroll
    for (int j = 0; j < 8; j++) {
        int t = t0 + j;
        val[j] = (t < T_TOK);
        const float* p = (t == 0) ? cls : (val[j] ? x + (size_t)(t - 1) * D_MODEL : cls);
        rp[j] = (const float4*)p;
    }

    float acc[8][8];
#pragma unroll
    for (int j = 0; j < 8; j++)
#pragma unroll
        for (int h = 0; h < 8; h++) acc[j][h] = 0.f;

#pragma unroll
    for (int i = 0; i < 8; i++) {
        int f = i * 32 + lane;
        float4 u4[8];
#pragma unroll
        for (int h = 0; h < 8; h++) u4[h] = su4[h * 256 + f];
#pragma unroll
        for (int j = 0; j < 8; j++) {
            float4 tv = rp[j][f];
#pragma unroll
            for (int h = 0; h < 8; h++) {
                acc[j][h] += tv.x * u4[h].x;
                acc[j][h] += tv.y * u4[h].y;
                acc[j][h] += tv.z * u4[h].z;
                acc[j][h] += tv.w * u4[h].w;
            }
        }
    }

#pragma unroll
    for (int j = 0; j < 8; j++)
#pragma unroll
        for (int h = 0; h < 8; h++) {
            float s = acc[j][h];
#pragma unroll
            for (int o = 16; o; o >>= 1) s += __shfl_xor_sync(0xffffffffu, s, o);
            acc[j][h] = s;
        }

    float myv[8];
#pragma unroll
    for (int j = 0; j < 8; j++) {
        float v = acc[j][0];
#pragma unroll
        for (int h = 1; h < 8; h++) if (lane == h) v = acc[j][h];
        myv[j] = v;
    }

    if (lane < N_HEADS) {
        float c = sc[lane];
#pragma unroll
        for (int j = 0; j < 8; j++) {
            float s = val[j] ? (myv[j] + c) : -3e38f;
            ss[lane][w * 8 + j] = s;
            if (val[j]) g_scores[lane * SS + t0 + j] = s;
        }
    }
    __syncthreads();

    if (w < N_HEADS) {
        int h = w;
        float v0 = ss[h][lane], v1 = ss[h][lane + 32];
        float m = fmaxf(v0, v1);
#pragma unroll
        for (int o = 16; o; o >>= 1) m = fmaxf(m, __shfl_xor_sync(0xffffffffu, m, o));
        float e0 = __expf(v0 - m), e1 = __expf(v1 - m);
        sp[h][lane] = e0;
        sp[h][lane + 32] = e1;
        float z = warp_sum(e0 + e1);
        if (lane == 0) {
            g_pM[blockIdx.x * N_HEADS + h] = m;
            g_pZ[blockIdx.x * N_HEADS + h] = z;
        }
    }
    __syncthreads();

    float4 wacc[N_HEADS];
#pragma unroll
    for (int h = 0; h < N_HEADS; h++) wacc[h] = make_float4(0.f, 0.f, 0.f, 0.f);
    int d4 = tid * 4;
    int base = blockIdx.x * 64;
    int n = min(64, T_TOK - base);

#pragma unroll 4
    for (int i = 0; i < n; i++) {
        int gt = base + i;
        const float* tp = (gt == 0) ? cls : x + (size_t)(gt - 1) * D_MODEL;
        float4 tv = *reinterpret_cast<const float4*>(tp + d4);
#pragma unroll
        for (int h = 0; h < N_HEADS; h++) {
            float p = sp[h][i];
            wacc[h].x += p * tv.x;
            wacc[h].y += p * tv.y;
            wacc[h].z += p * tv.z;
            wacc[h].w += p * tv.w;
        }
    }
#pragma unroll
    for (int h = 0; h < N_HEADS; h++)
        *reinterpret_cast<float4*>(
            &g_wpart[(size_t)blockIdx.x * (N_HEADS * D_MODEL) + h * D_MODEL + d4]) = wacc[h];
}

// ---- finalize: blocks 0..63 merge w partials (8 threads/float4-col);
//      blocks 64..95 write A -------------------------------------------------
__global__ __launch_bounds__(256)
void finalize2(float* __restrict__ out, int out_size) {
    __shared__ float sM[N_HEADS], sZi[N_HEADS];
    __shared__ float sf[S_NBLK];

    int tid = threadIdx.x;
    int w = tid >> 5, lane = tid & 31;

    // global (M, Z) per head
    if (w < N_HEADS) {
        int h = w;
        float m = -3e38f, z = 0.f;
        for (int b = lane; b < S_NBLK; b += 32) {
            float bm = g_pM[b * N_HEADS + h];
            float bz = g_pZ[b * N_HEADS + h];
            float nm = fmaxf(m, bm);
            z = z * __expf(m - nm) + bz * __expf(bm - nm);
            m = nm;
        }
#pragma unroll
        for (int o = 16; o; o >>= 1) {
            float om = __shfl_xor_sync(0xffffffffu, m, o);
            float oz = __shfl_xor_sync(0xffffffffu, z, o);
            float nm = fmaxf(m, om);
            z = z * __expf(m - nm) + oz * __expf(om - nm);
            m = nm;
        }
        if (lane == 0) { sM[h] = m; sZi[h] = 1.0f / z; }
    }
    __syncthreads();

    if (blockIdx.x < 64) {
        int idx0 = blockIdx.x * 128;
        int h = idx0 >> 10;
        float M = sM[h], Zi = sZi[h];
        for (int b = tid; b < S_NBLK; b += 256)
            sf[b] = __expf(g_pM[b * N_HEADS + h] - M) * Zi;
        __syncthreads();

        int col4 = (idx0 >> 2) + (tid >> 3);
        int sub = tid & 7;
        const float4* wp4 = (const float4*)g_wpart;
        float4 a = make_float4(0.f, 0.f, 0.f, 0.f);
        for (int b = sub; b < S_NBLK; b += 8) {
            float4 v = wp4[(size_t)b * 2048 + col4];
            float s = sf[b];
            a.x += s * v.x; a.y += s * v.y; a.z += s * v.z; a.w += s * v.w;
        }
#pragma unroll
        for (int o = 4; o; o >>= 1) {
            a.x += __shfl_xor_sync(0xffffffffu, a.x, o);
            a.y += __shfl_xor_sync(0xffffffffu, a.y, o);
            a.z += __shfl_xor_sync(0xffffffffu, a.z, o);
            a.w += __shfl_xor_sync(0xffffffffu, a.w, o);
        }
        if (sub == 0) ((float4*)g_w)[col4] = a;
    } else {
        int s = (blockIdx.x - 64) * 256 + tid;
        float a = 0.f;
#pragma unroll
        for (int h = 0; h < N_HEADS; h++)
            a += __expf(g_scores[h * SS + s + 1] - sM[h]) * sZi[h];
        a *= 0.125f;
        int oi = 7 + s;
        if (oi < out_size) out[oi] = a;
    }
}

// logits, softmax, argmax -> out[0..6]
__global__ void final_kernel(const float* __restrict__ Wc, const float* __restrict__ bc,
                             float* __restrict__ out, int out_size) {
    __shared__ float slog[2];
    int wid = threadIdx.x >> 5, lane = threadIdx.x & 31;
    if (wid < 2) {
        const float4* wr = (const float4*)(Wc + (size_t)wid * D_MODEL);
        const float4* vv = (const float4*)g_out0;
        float acc = 0.f;
#pragma unroll
        for (int i = 0; i < D_MODEL / 128; i++) {
            float4 a = wr[i * 32 + lane];
            float4 c = vv[i * 32 + lane];
            acc += a.x * c.x + a.y * c.y + a.z * c.z + a.w * c.w;
        }
        acc = warp_sum(acc);
        if (lane == 0) slog[wid] = acc + bc[wid];
    }
    __syncthreads();
    if (threadIdx.x == 0 && out_size >= 7) {
        float l0 = slog[0], l1 = slog[1];
        float mx = fmaxf(l0, l1);
        float e0 = __expf(l0 - mx), e1 = __expf(l1 - mx);
        float z = e0 + e1;
        float p0 = e0 / z, p1 = e1 / z;
        float am = (p1 > p0) ? 1.0f : 0.0f;
        out[0] = l0; out[1] = l1;
        out[2] = p0; out[3] = p1;
        out[4] = am;
        out[5] = p0; out[6] = p1;
    }
}

// ---------------- launch -----------------------------------------------------
extern "C" void kernel_launch(void* const* d_in, const int* in_sizes, int n_in,
                              void* d_out, int out_size) {
    const float* x   = (const float*)d_in[0];
    const float* cls = (const float*)d_in[1];
    const float* Wq  = (const float*)d_in[2];
    const float* bq  = (const float*)d_in[3];
    const float* Wk  = (const float*)d_in[4];
    const float* bk  = (const float*)d_in[5];
    const float* Wv  = (const float*)d_in[6];
    const float* bv  = (const float*)d_in[7];
    const float* Wo  = (const float*)d_in[8];
    const float* bo  = (const float*)d_in[9];
    const float* Wc  = (const float*)d_in[10];
    const float* bc  = (const float*)d_in[11];
    float* out = (float*)d_out;

    float* gq0;   cudaGetSymbolAddress((void**)&gq0,   g_q0);
    float* gattn; cudaGetSymbolAddress((void**)&gattn, g_attn0);
    float* gout0; cudaGetSymbolAddress((void**)&gout0, g_out0);

    matvec_warp<<<128, 256>>>(Wq, cls, bq, gq0);        // q0
    compute_u<<<33, 256>>>(Wk, bk);                     // u, c
    fused_kernel<<<S_NBLK, 256>>>(x, cls);              // scores + partials (1 x pass)
    finalize2<<<96, 256>>>(out, out_size);              // merge -> w, write A
    attn0_kernel<<<128, 256>>>(Wv, bv);                 // attn0
    matvec_warp<<<128, 256>>>(Wo, gattn, bo, gout0);    // out0
    final_kernel<<<1, 64>>>(Wc, bc, out, out_size);     // logits etc.
}